// round 1
// baseline (speedup 1.0000x reference)
#include <cuda_runtime.h>
#include <cstdint>
#include <cstddef>

// Problem dims (fixed by the dataset)
#define B_ 64
#define S_ 1024
#define I_ 512
#define H_ 1024
#define O_ 512

// ---------------- scratch (no cudaMalloc allowed) ----------------
__device__ float g_xp[(size_t)B_ * S_ * H_];  // x-projection (B*S, H)   256MB
__device__ float g_hs[(size_t)B_ * S_ * H_];  // hidden states (B*S, H)  256MB
__device__ unsigned g_bar;                    // grid barrier counter

// Accurate tanh, robust under --use_fast_math (expf->__expf is ~2^-21 rel).
__device__ __forceinline__ float tanh_acc(float x) {
    float ax = fabsf(x);
    float e  = __expf(-2.0f * ax);          // in (0,1]
    float r  = (1.0f - e) / (1.0f + e);     // tanh(|x|), numerically stable
    return copysignf(r, x);
}

__global__ void zero_bar() { g_bar = 0u; }

// ---------------- generic NT GEMM: C[m,n] = sum_k A[m,k]*Bm[n,k] + bias0[n] (+bias1[n])
// BM=BN=128, BK=16, 256 threads, 8x8 register tile per thread. M,N,K divisible by tile.
__global__ void __launch_bounds__(256)
gemm_nt_bias(const float* __restrict__ A, const float* __restrict__ Bm,
             const float* __restrict__ bias0, const float* __restrict__ bias1,
             float* __restrict__ C, int M, int N, int K)
{
    const int BK = 16;
    __shared__ float As[16][128 + 4];
    __shared__ float Bs[16][128 + 4];

    int t  = threadIdx.x;
    int tx = t & 15;          // 0..15 -> N direction
    int ty = t >> 4;          // 0..15 -> M direction
    int bm = blockIdx.y * 128;
    int bn = blockIdx.x * 128;

    float acc[8][8];
#pragma unroll
    for (int i = 0; i < 8; i++)
#pragma unroll
        for (int j = 0; j < 8; j++) acc[i][j] = 0.0f;

    for (int kc = 0; kc < K; kc += BK) {
        // load 128x16 tiles of A and Bm (as float4 along K), store K-major in smem
#pragma unroll
        for (int i = 0; i < 2; i++) {
            int id = t + i * 256;        // 0..511
            int r  = id >> 2;            // 0..127
            int c4 = id & 3;             // 0..3 (float4 within 16 k's)
            float4 va = *(const float4*)(A  + (size_t)(bm + r) * K + kc + c4 * 4);
            As[c4 * 4 + 0][r] = va.x; As[c4 * 4 + 1][r] = va.y;
            As[c4 * 4 + 2][r] = va.z; As[c4 * 4 + 3][r] = va.w;
            float4 vb = *(const float4*)(Bm + (size_t)(bn + r) * K + kc + c4 * 4);
            Bs[c4 * 4 + 0][r] = vb.x; Bs[c4 * 4 + 1][r] = vb.y;
            Bs[c4 * 4 + 2][r] = vb.z; Bs[c4 * 4 + 3][r] = vb.w;
        }
        __syncthreads();
#pragma unroll
        for (int k = 0; k < BK; k++) {
            float a[8], b[8];
#pragma unroll
            for (int i = 0; i < 8; i++) a[i] = As[k][ty * 8 + i];
#pragma unroll
            for (int j = 0; j < 8; j++) b[j] = Bs[k][tx * 8 + j];
#pragma unroll
            for (int i = 0; i < 8; i++)
#pragma unroll
                for (int j = 0; j < 8; j++) acc[i][j] += a[i] * b[j];
        }
        __syncthreads();
    }

    float bs[8];
#pragma unroll
    for (int j = 0; j < 8; j++) {
        int n = bn + tx * 8 + j;
        bs[j] = bias0[n] + (bias1 ? bias1[n] : 0.0f);
    }
#pragma unroll
    for (int i = 0; i < 8; i++) {
        size_t row = (size_t)(bm + ty * 8 + i) * N + bn + tx * 8;
        float4 v0 = make_float4(acc[i][0] + bs[0], acc[i][1] + bs[1],
                                acc[i][2] + bs[2], acc[i][3] + bs[3]);
        float4 v1 = make_float4(acc[i][4] + bs[4], acc[i][5] + bs[5],
                                acc[i][6] + bs[6], acc[i][7] + bs[7]);
        *(float4*)(C + row)     = v0;
        *(float4*)(C + row + 4) = v1;
    }
}

// ---------------- persistent recurrence ----------------
// 128 blocks x 128 threads, all co-resident. Block bn owns hidden columns
// [bn*8, bn*8+8). Its 8 rows of W_hh (32KB) live in SMEM for all 1024 steps.
// Each step: h_new[b][n] = tanh(xp[b][s][n] + sum_k h_prev[b][k]*W_hh[n][k]),
// then one monotonic-counter grid barrier.
#define RB 128        // blocks
#define RT 128        // threads/block
#define KC 128        // K chunk staged in smem per iteration
// smem: Wsm 8*1024 floats (32768B) + hsm float4[64][33] (33792B) = 66560B
#define REC_SMEM (8 * H_ * 4 + 64 * 33 * 16)

__global__ void __launch_bounds__(RT, 1)
rnn_recurrence(const float* __restrict__ xp, const float* __restrict__ Whh,
               const float* __restrict__ h0, float* __restrict__ hs)
{
    extern __shared__ float sm[];
    float4* Wsm4 = (float4*)sm;                  // [8][256] float4 (K-major rows)
    float4* hsm  = (float4*)(sm + 8 * H_);       // [64][33] float4 (32 used + 1 pad)

    const int t  = threadIdx.x;                  // 0..127
    const int bn = blockIdx.x;                   // 0..127
    const int n0 = bn * 8;

    // Load this block's 8 rows of W_hh into smem (stays for all steps).
    for (int i = t; i < 8 * (H_ / 4); i += RT) { // 2048 float4
        int r = i >> 8;                          // row 0..7
        int c = i & 255;                         // float4 col
        Wsm4[r * 256 + c] = *((const float4*)(Whh + (size_t)(n0 + r) * H_) + c);
    }
    __syncthreads();

    const int m   = t & 63;                      // batch index this thread computes
    const int dup = t >> 6;                      // 0/1 -> which 4 of the 8 columns

    unsigned target = 0;
    for (int s = 0; s < S_; s++) {
        const float* hsrc;
        size_t rstride;
        if (s == 0) { hsrc = h0;                        rstride = H_; }
        else        { hsrc = hs + (size_t)(s - 1) * H_; rstride = (size_t)S_ * H_; }

        float acc[4] = {0.f, 0.f, 0.f, 0.f};

        for (int kc = 0; kc < H_; kc += KC) {
            // stage h_prev[0:64, kc:kc+128] into smem (L2 loads, L1-bypassing)
#pragma unroll
            for (int i = 0; i < 16; i++) {
                int id = i * RT + t;             // 0..2047
                int r  = id >> 5;                // 0..63
                int c  = id & 31;                // 0..31 float4
                hsm[r * 33 + c] = __ldcg((const float4*)(hsrc + (size_t)r * rstride + kc) + c);
            }
            __syncthreads();

            const int kb4 = kc >> 2;
#pragma unroll
            for (int k4 = 0; k4 < KC / 4; k4++) {
                float4 h4 = hsm[m * 33 + k4];
#pragma unroll
                for (int j = 0; j < 4; j++) {
                    float4 w = Wsm4[(dup * 4 + j) * 256 + kb4 + k4];
                    acc[j] += h4.x * w.x;
                    acc[j] += h4.y * w.y;
                    acc[j] += h4.z * w.z;
                    acc[j] += h4.w * w.w;
                }
            }
            __syncthreads();
        }

        // epilogue: 4 consecutive outputs per thread
        size_t orow = ((size_t)m * S_ + s) * H_ + n0 + dup * 4;
        float4 xv = *(const float4*)(xp + orow);
        float4 hv;
        hv.x = tanh_acc(acc[0] + xv.x);
        hv.y = tanh_acc(acc[1] + xv.y);
        hv.z = tanh_acc(acc[2] + xv.z);
        hv.w = tanh_acc(acc[3] + xv.w);
        *(float4*)(hs + orow) = hv;

        // grid barrier (monotonic counter; all RB blocks are co-resident)
        target += RB;
        __syncthreads();
        if (t == 0) {
            __threadfence();
            atomicAdd(&g_bar, 1u);
            while (*(volatile unsigned*)&g_bar < target) { }
        }
        __syncthreads();
        __threadfence();
    }
}

// last_hidden[b][k] = hs[b][S-1][k]
__global__ void copy_last(const float* __restrict__ hs, float* __restrict__ out)
{
    int i = blockIdx.x * 256 + threadIdx.x;      // 0..B*H-1
    int b = i >> 10, k = i & (H_ - 1);
    out[i] = hs[((size_t)b * S_ + (S_ - 1)) * H_ + k];
}

// ---------------- launch ----------------
extern "C" void kernel_launch(void* const* d_in, const int* in_sizes, int n_in,
                              void* d_out, int out_size)
{
    const float* inputs = (const float*)d_in[0];
    const float* h0     = (const float*)d_in[1];
    const float* W_ih   = (const float*)d_in[2];
    const float* b_ih   = (const float*)d_in[3];
    const float* W_hh   = (const float*)d_in[4];
    const float* b_hh   = (const float*)d_in[5];
    const float* W_ho   = (const float*)d_in[6];
    const float* b_ho   = (const float*)d_in[7];
    float* out = (float*)d_out;

    float *xp, *hs;
    cudaGetSymbolAddress((void**)&xp, g_xp);
    cudaGetSymbolAddress((void**)&hs, g_hs);

    cudaFuncSetAttribute(rnn_recurrence,
                         cudaFuncAttributeMaxDynamicSharedMemorySize, REC_SMEM);

    zero_bar<<<1, 1>>>();

    // xp = inputs @ W_ih^T + b_ih + b_hh   (M=B*S, N=H, K=I)
    dim3 g1(H_ / 128, (B_ * S_) / 128);
    gemm_nt_bias<<<g1, 256>>>(inputs, W_ih, b_ih, b_hh, xp, B_ * S_, H_, I_);

    // sequential scan over time, persistent kernel
    rnn_recurrence<<<RB, RT, REC_SMEM>>>(xp, W_hh, h0, hs);

    // outputs = hs @ W_ho^T + b_ho         (M=B*S, N=O, K=H)
    dim3 g2(O_ / 128, (B_ * S_) / 128);
    gemm_nt_bias<<<g2, 256>>>(hs, W_ho, b_ho, nullptr, out, B_ * S_, O_, H_);

    // last_hidden appended after outputs
    copy_last<<<(B_ * H_) / 256, 256>>>(hs, out + (size_t)B_ * S_ * O_);
}

// round 2
// speedup vs baseline: 1.1111x; 1.1111x over previous
#include <cuda_runtime.h>
#include <cstdint>
#include <cstddef>

// Problem dims (fixed by the dataset)
#define B_ 64
#define S_ 1024
#define I_ 512
#define H_ 1024
#define O_ 512

typedef unsigned long long ull;

// ---------------- scratch (no cudaMalloc allowed) ----------------
__device__ float g_xp[(size_t)B_ * S_ * H_];  // x-projection (B*S, H)
__device__ float g_hs[(size_t)B_ * S_ * H_];  // hidden states [b][s][H]
__device__ unsigned g_bar;                    // grid barrier counter

// ---------------- helpers ----------------
__device__ __forceinline__ ull fma2(ull a, ull b, ull c) {
    ull d;
    asm("fma.rn.f32x2 %0, %1, %2, %3;" : "=l"(d) : "l"(a), "l"(b), "l"(c));
    return d;
}
__device__ __forceinline__ ull add2(ull a, ull b) {
    ull d;
    asm("add.rn.f32x2 %0, %1, %2;" : "=l"(d) : "l"(a), "l"(b));
    return d;
}
__device__ __forceinline__ ull pack2(float x, float y) {
    ull d; asm("mov.b64 %0, {%1, %2};" : "=l"(d) : "f"(x), "f"(y)); return d;
}
__device__ __forceinline__ void unpack2(ull v, float& lo, float& hi) {
    asm("mov.b64 {%0, %1}, %2;" : "=f"(lo), "=f"(hi) : "l"(v));
}
__device__ __forceinline__ uint32_t smem_u32(const void* p) {
    uint32_t a;
    asm("{ .reg .u64 t; cvta.to.shared.u64 t, %1; cvt.u32.u64 %0, t; }"
        : "=r"(a) : "l"(p));
    return a;
}
__device__ __forceinline__ void cp16(uint32_t saddr, const void* g) {
    asm volatile("cp.async.cg.shared.global [%0], [%1], 16;" :: "r"(saddr), "l"(g));
}
#define CP_COMMIT() asm volatile("cp.async.commit_group;" ::: "memory")
#define CP_WAIT(n)  asm volatile("cp.async.wait_group %0;" :: "n"(n) : "memory")

// Accurate tanh, robust under --use_fast_math.
__device__ __forceinline__ float tanh_acc(float x) {
    float ax = fabsf(x);
    float e  = __expf(-2.0f * ax);
    float r  = (1.0f - e) / (1.0f + e);
    return copysignf(r, x);
}

__global__ void zero_bar() { g_bar = 0u; }

// ---------------- NT GEMM with f32x2 FMA ----------------
// C[m,n] = sum_k A[m,k]*Bm[n,k] + bias0[n] (+bias1[n]). BM=BN=128, BK=16,
// 256 threads, 8x8 register tile per thread packed as 8x4 f32x2.
__global__ void __launch_bounds__(256)
gemm_nt_bias(const float* __restrict__ A, const float* __restrict__ Bm,
             const float* __restrict__ bias0, const float* __restrict__ bias1,
             float* __restrict__ C, int M, int N, int K)
{
    const int BK = 16;
    __shared__ float As[16][128 + 4];
    __shared__ float Bs[16][128 + 4];

    int t  = threadIdx.x;
    int tx = t & 15;          // N direction
    int ty = t >> 4;          // M direction
    int bm = blockIdx.y * 128;
    int bn = blockIdx.x * 128;

    ull acc2[8][4];
#pragma unroll
    for (int i = 0; i < 8; i++)
#pragma unroll
        for (int j = 0; j < 4; j++) acc2[i][j] = 0ull;

    for (int kc = 0; kc < K; kc += BK) {
#pragma unroll
        for (int i = 0; i < 2; i++) {
            int id = t + i * 256;
            int r  = id >> 2;
            int c4 = id & 3;
            float4 va = *(const float4*)(A  + (size_t)(bm + r) * K + kc + c4 * 4);
            As[c4 * 4 + 0][r] = va.x; As[c4 * 4 + 1][r] = va.y;
            As[c4 * 4 + 2][r] = va.z; As[c4 * 4 + 3][r] = va.w;
            float4 vb = *(const float4*)(Bm + (size_t)(bn + r) * K + kc + c4 * 4);
            Bs[c4 * 4 + 0][r] = vb.x; Bs[c4 * 4 + 1][r] = vb.y;
            Bs[c4 * 4 + 2][r] = vb.z; Bs[c4 * 4 + 3][r] = vb.w;
        }
        __syncthreads();
#pragma unroll
        for (int k = 0; k < BK; k++) {
            float4 a0 = *(const float4*)&As[k][ty * 8];
            float4 a1 = *(const float4*)&As[k][ty * 8 + 4];
            ulonglong2 b0 = *(const ulonglong2*)&Bs[k][tx * 8];
            ulonglong2 b1 = *(const ulonglong2*)&Bs[k][tx * 8 + 4];
            ull bb[4] = { b0.x, b0.y, b1.x, b1.y };
            ull a2[8];
            a2[0] = pack2(a0.x, a0.x); a2[1] = pack2(a0.y, a0.y);
            a2[2] = pack2(a0.z, a0.z); a2[3] = pack2(a0.w, a0.w);
            a2[4] = pack2(a1.x, a1.x); a2[5] = pack2(a1.y, a1.y);
            a2[6] = pack2(a1.z, a1.z); a2[7] = pack2(a1.w, a1.w);
#pragma unroll
            for (int i = 0; i < 8; i++)
#pragma unroll
                for (int j = 0; j < 4; j++)
                    acc2[i][j] = fma2(a2[i], bb[j], acc2[i][j]);
        }
        __syncthreads();
    }

    float bs[8];
#pragma unroll
    for (int j = 0; j < 8; j++) {
        int n = bn + tx * 8 + j;
        bs[j] = bias0[n] + (bias1 ? bias1[n] : 0.0f);
    }
#pragma unroll
    for (int i = 0; i < 8; i++) {
        float acc[8];
#pragma unroll
        for (int j = 0; j < 4; j++)
            unpack2(acc2[i][j], acc[2 * j], acc[2 * j + 1]);
        size_t row = (size_t)(bm + ty * 8 + i) * N + bn + tx * 8;
        float4 v0 = make_float4(acc[0] + bs[0], acc[1] + bs[1],
                                acc[2] + bs[2], acc[3] + bs[3]);
        float4 v1 = make_float4(acc[4] + bs[4], acc[5] + bs[5],
                                acc[6] + bs[6], acc[7] + bs[7]);
        *(float4*)(C + row)     = v0;
        *(float4*)(C + row + 4) = v1;
    }
}

// ---------------- persistent recurrence ----------------
// 128 blocks x 256 threads, all co-resident (1 block/SM).
// Block bx: colg = bx>>1 (16 hidden cols), batg = bx&1 (32 batches).
// W_hh slice (16 x 1024 f32 = 64KB) lives in SMEM for all steps.
// h_prev staged per step in two 512-K chunks via cp.async (double buffer).
// Inner loop: f32x2 FMA, 4 independent accumulator chains per thread.
#define RBLK 128
#define RTHR 256
#define CHK  512                          // K per chunk
#define HP4  129                          // float4 pitch per h row (128 + 1 pad)
#define W_F4 (16 * 256)                   // W slice float4 count
#define HB_F4 (32 * HP4)                  // one h buffer float4 count
#define REC_SMEM ((W_F4 + 2 * HB_F4) * 16)

__global__ void __launch_bounds__(RTHR, 1)
rnn_recurrence(const float* __restrict__ xp, const float* __restrict__ Whh,
               const float* __restrict__ h0, float* __restrict__ hs)
{
    extern __shared__ float4 sm4[];
    float4* Wsm = sm4;                    // [16][256]
    float4* hb[2] = { sm4 + W_F4, sm4 + W_F4 + HB_F4 };

    const int t    = threadIdx.x;
    const int bx   = blockIdx.x;
    const int n0   = (bx >> 1) * 16;      // first hidden col of this block
    const int m0   = (bx & 1) * 32;       // first batch of this block
    const int m    = t & 31;              // batch lane
    const int dup  = t >> 5;              // 0..7 -> cols dup*2, dup*2+1

    // Load W_hh slice once (16 rows x 1024 floats).
    for (int i = t; i < W_F4; i += RTHR) {
        int r = i >> 8, c = i & 255;
        Wsm[r * 256 + c] = *((const float4*)(Whh + (size_t)(n0 + r) * H_) + c);
    }
    __syncthreads();

    const ulonglong2* Wu  = (const ulonglong2*)Wsm;
    uint32_t hb_u32[2] = { smem_u32(hb[0]), smem_u32(hb[1]) };

    const int r16 = t >> 3;               // staging row 0..31 (8 thr/row)
    const int c16 = t & 7;                // staging col group

    unsigned target = 0;
    for (int s = 0; s < S_; s++) {
        const float* hsrc;
        size_t rstride;
        if (s == 0) { hsrc = h0 + (size_t)m0 * H_;                 rstride = H_; }
        else        { hsrc = hs + ((size_t)m0 * S_ + (s - 1)) * H_; rstride = (size_t)S_ * H_; }

        // Stage both 512-K chunks with cp.async; chunk1 overlaps chunk0 compute.
#pragma unroll
        for (int ch = 0; ch < 2; ch++) {
            const int koff = ch * CHK;
#pragma unroll
            for (int i = 0; i < 16; i++) {
                int id = i * RTHR + t;    // 0..4095
                int r  = id >> 7;         // 0..31
                int c  = id & 127;        // float4 col in chunk
                cp16(hb_u32[ch] + (uint32_t)(r * HP4 + c) * 16,
                     hsrc + (size_t)r * rstride + koff + c * 4);
            }
            CP_COMMIT();
        }

        ull accA0 = 0, accB0 = 0, accA1 = 0, accB1 = 0;   // cols j0, j0+1
        const int j0 = dup * 2;

#pragma unroll
        for (int ch = 0; ch < 2; ch++) {
            if (ch == 0) { CP_WAIT(1); } else { CP_WAIT(0); }
            __syncthreads();
            const ulonglong2* hbu = (const ulonglong2*)hb[ch];
            const int kb4 = (ch * CHK) >> 2;
#pragma unroll 8
            for (int k4 = 0; k4 < CHK / 4; k4++) {
                ulonglong2 h2 = hbu[m * HP4 + k4];
                ulonglong2 w0 = Wu[(j0 + 0) * 256 + kb4 + k4];
                ulonglong2 w1 = Wu[(j0 + 1) * 256 + kb4 + k4];
                accA0 = fma2(h2.x, w0.x, accA0);
                accB0 = fma2(h2.y, w0.y, accB0);
                accA1 = fma2(h2.x, w1.x, accA1);
                accB1 = fma2(h2.y, w1.y, accB1);
            }
            __syncthreads();   // allow next-step restage of this buffer
        }

        // epilogue: 2 outputs per thread
        float l0, h0v, l1, h1v;
        unpack2(add2(accA0, accB0), l0, h0v);
        unpack2(add2(accA1, accB1), l1, h1v);
        size_t orow = ((size_t)(m0 + m) * S_ + s) * H_ + n0 + j0;
        float2 xv = *(const float2*)(xp + orow);
        float2 hv;
        hv.x = tanh_acc(l0 + h0v + xv.x);
        hv.y = tanh_acc(l1 + h1v + xv.y);
        *(float2*)(hs + orow) = hv;

        // grid barrier (monotonic counter; all RBLK blocks co-resident)
        target += RBLK;
        __syncthreads();
        if (t == 0) {
            __threadfence();
            atomicAdd(&g_bar, 1u);
            while (*(volatile unsigned*)&g_bar < target) { }
        }
        __syncthreads();
        __threadfence();
    }
}

// last_hidden[b][k] = hs[b][S-1][k]
__global__ void copy_last(const float* __restrict__ hs, float* __restrict__ out)
{
    int i = blockIdx.x * 256 + threadIdx.x;
    int b = i >> 10, k = i & (H_ - 1);
    out[i] = hs[((size_t)b * S_ + (S_ - 1)) * H_ + k];
}

// ---------------- launch ----------------
extern "C" void kernel_launch(void* const* d_in, const int* in_sizes, int n_in,
                              void* d_out, int out_size)
{
    const float* inputs = (const float*)d_in[0];
    const float* h0     = (const float*)d_in[1];
    const float* W_ih   = (const float*)d_in[2];
    const float* b_ih   = (const float*)d_in[3];
    const float* W_hh   = (const float*)d_in[4];
    const float* b_hh   = (const float*)d_in[5];
    const float* W_ho   = (const float*)d_in[6];
    const float* b_ho   = (const float*)d_in[7];
    float* out = (float*)d_out;

    float *xp, *hs;
    cudaGetSymbolAddress((void**)&xp, g_xp);
    cudaGetSymbolAddress((void**)&hs, g_hs);

    cudaFuncSetAttribute(rnn_recurrence,
                         cudaFuncAttributeMaxDynamicSharedMemorySize, REC_SMEM);

    zero_bar<<<1, 1>>>();

    // xp = inputs @ W_ih^T + b_ih + b_hh   (M=B*S, N=H, K=I)
    dim3 g1(H_ / 128, (B_ * S_) / 128);
    gemm_nt_bias<<<g1, 256>>>(inputs, W_ih, b_ih, b_hh, xp, B_ * S_, H_, I_);

    // sequential scan, persistent kernel
    rnn_recurrence<<<RBLK, RTHR, REC_SMEM>>>(xp, W_hh, h0, hs);

    // outputs = hs @ W_ho^T + b_ho         (M=B*S, N=O, K=H)
    dim3 g2(O_ / 128, (B_ * S_) / 128);
    gemm_nt_bias<<<g2, 256>>>(hs, W_ho, b_ho, nullptr, out, B_ * S_, O_, H_);

    // last_hidden appended after outputs
    copy_last<<<(B_ * H_) / 256, 256>>>(hs, out + (size_t)B_ * S_ * O_);
}

// round 3
// speedup vs baseline: 1.6724x; 1.5052x over previous
#include <cuda_runtime.h>
#include <cstdint>
#include <cstddef>

// Problem dims (fixed by the dataset)
#define B_ 64
#define S_ 1024
#define I_ 512
#define H_ 1024
#define O_ 512

typedef unsigned long long ull;

// ---------------- scratch (no cudaMalloc allowed) ----------------
__device__ float g_xp[(size_t)B_ * S_ * H_];  // x-projection (B*S, H)
__device__ float g_hs[(size_t)B_ * S_ * H_];  // hidden states [b][s][H]
__device__ unsigned g_bar;                    // grid barrier counter

// ---------------- helpers ----------------
__device__ __forceinline__ ull fma2(ull a, ull b, ull c) {
    ull d;
    asm("fma.rn.f32x2 %0, %1, %2, %3;" : "=l"(d) : "l"(a), "l"(b), "l"(c));
    return d;
}
__device__ __forceinline__ ull add2(ull a, ull b) {
    ull d;
    asm("add.rn.f32x2 %0, %1, %2;" : "=l"(d) : "l"(a), "l"(b));
    return d;
}
__device__ __forceinline__ ull pack2(float x, float y) {
    ull d; asm("mov.b64 %0, {%1, %2};" : "=l"(d) : "f"(x), "f"(y)); return d;
}
__device__ __forceinline__ void unpack2(ull v, float& lo, float& hi) {
    asm("mov.b64 {%0, %1}, %2;" : "=f"(lo), "=f"(hi) : "l"(v));
}
__device__ __forceinline__ uint32_t smem_u32(const void* p) {
    uint32_t a;
    asm("{ .reg .u64 t; cvta.to.shared.u64 t, %1; cvt.u32.u64 %0, t; }"
        : "=r"(a) : "l"(p));
    return a;
}
__device__ __forceinline__ void cp16(uint32_t saddr, const void* g) {
    asm volatile("cp.async.cg.shared.global [%0], [%1], 16;" :: "r"(saddr), "l"(g));
}
#define CP_COMMIT() asm volatile("cp.async.commit_group;" ::: "memory")
#define CP_WAIT(n)  asm volatile("cp.async.wait_group %0;" :: "n"(n) : "memory")

// Accurate tanh, robust under --use_fast_math.
__device__ __forceinline__ float tanh_acc(float x) {
    float ax = fabsf(x);
    float e  = __expf(-2.0f * ax);
    float r  = (1.0f - e) / (1.0f + e);
    return copysignf(r, x);
}

__global__ void zero_bar() { g_bar = 0u; }

// ---------------- NT GEMM with f32x2 FMA ----------------
__global__ void __launch_bounds__(256)
gemm_nt_bias(const float* __restrict__ A, const float* __restrict__ Bm,
             const float* __restrict__ bias0, const float* __restrict__ bias1,
             float* __restrict__ C, int M, int N, int K)
{
    const int BK = 16;
    __shared__ float As[16][128 + 4];
    __shared__ float Bs[16][128 + 4];

    int t  = threadIdx.x;
    int tx = t & 15;
    int ty = t >> 4;
    int bm = blockIdx.y * 128;
    int bn = blockIdx.x * 128;

    ull acc2[8][4];
#pragma unroll
    for (int i = 0; i < 8; i++)
#pragma unroll
        for (int j = 0; j < 4; j++) acc2[i][j] = 0ull;

    for (int kc = 0; kc < K; kc += BK) {
#pragma unroll
        for (int i = 0; i < 2; i++) {
            int id = t + i * 256;
            int r  = id >> 2;
            int c4 = id & 3;
            float4 va = *(const float4*)(A  + (size_t)(bm + r) * K + kc + c4 * 4);
            As[c4 * 4 + 0][r] = va.x; As[c4 * 4 + 1][r] = va.y;
            As[c4 * 4 + 2][r] = va.z; As[c4 * 4 + 3][r] = va.w;
            float4 vb = *(const float4*)(Bm + (size_t)(bn + r) * K + kc + c4 * 4);
            Bs[c4 * 4 + 0][r] = vb.x; Bs[c4 * 4 + 1][r] = vb.y;
            Bs[c4 * 4 + 2][r] = vb.z; Bs[c4 * 4 + 3][r] = vb.w;
        }
        __syncthreads();
#pragma unroll
        for (int k = 0; k < BK; k++) {
            float4 a0 = *(const float4*)&As[k][ty * 8];
            float4 a1 = *(const float4*)&As[k][ty * 8 + 4];
            ulonglong2 b0 = *(const ulonglong2*)&Bs[k][tx * 8];
            ulonglong2 b1 = *(const ulonglong2*)&Bs[k][tx * 8 + 4];
            ull bb[4] = { b0.x, b0.y, b1.x, b1.y };
            ull a2[8];
            a2[0] = pack2(a0.x, a0.x); a2[1] = pack2(a0.y, a0.y);
            a2[2] = pack2(a0.z, a0.z); a2[3] = pack2(a0.w, a0.w);
            a2[4] = pack2(a1.x, a1.x); a2[5] = pack2(a1.y, a1.y);
            a2[6] = pack2(a1.z, a1.z); a2[7] = pack2(a1.w, a1.w);
#pragma unroll
            for (int i = 0; i < 8; i++)
#pragma unroll
                for (int j = 0; j < 4; j++)
                    acc2[i][j] = fma2(a2[i], bb[j], acc2[i][j]);
        }
        __syncthreads();
    }

    float bs[8];
#pragma unroll
    for (int j = 0; j < 8; j++) {
        int n = bn + tx * 8 + j;
        bs[j] = bias0[n] + (bias1 ? bias1[n] : 0.0f);
    }
#pragma unroll
    for (int i = 0; i < 8; i++) {
        float acc[8];
#pragma unroll
        for (int j = 0; j < 4; j++)
            unpack2(acc2[i][j], acc[2 * j], acc[2 * j + 1]);
        size_t row = (size_t)(bm + ty * 8 + i) * N + bn + tx * 8;
        float4 v0 = make_float4(acc[0] + bs[0], acc[1] + bs[1],
                                acc[2] + bs[2], acc[3] + bs[3]);
        float4 v1 = make_float4(acc[4] + bs[4], acc[5] + bs[5],
                                acc[6] + bs[6], acc[7] + bs[7]);
        *(float4*)(C + row)     = v0;
        *(float4*)(C + row + 4) = v1;
    }
}

// ---------------- persistent recurrence, W_hh in registers ----------------
// 128 blocks x 256 threads (1/SM). Block bx: cols n0=(bx>>2)*32 .. +32,
// batches m0=(bx&3)*16 .. +16. Warp w owns k-range [128w,128w+128); lane l
// owns column n0+l: 64 packed f32x2 W registers, persistent over all steps.
// Per step: cp.async-stage h[16][1024] (64KB), per-b inner loop of
// LDS.64-broadcast h + fma2 with register W; 8 k-partials reduced via smem.
#define RBLK 128
#define RTHR 256
#define PARTP 33                                   // partials col pitch
#define REC_SMEM ((16 * 1024 + 8 * 16 * PARTP) * 4)

__global__ void __launch_bounds__(RTHR, 1)
rnn_recurrence(const float* __restrict__ xp, const float* __restrict__ Whh,
               const float* __restrict__ h0, float* __restrict__ hs)
{
    extern __shared__ float sm[];
    float* hsm  = sm;                 // [16][1024]
    float* part = sm + 16 * 1024;     // [8][16][PARTP]

    const int t  = threadIdx.x;
    const int bx = blockIdx.x;
    const int n0 = (bx >> 2) * 32;    // first col of this block
    const int m0 = (bx & 3) * 16;     // first batch of this block
    const int w  = t >> 5;            // warp: k-range owner
    const int l  = t & 31;            // lane: column owner
    const int k0 = w * 128;

    // Load this lane's W_hh column-slice into registers (once).
    ull Wreg[64];
    {
        const float2* wrow = (const float2*)(Whh + (size_t)(n0 + l) * H_ + k0);
#pragma unroll
        for (int j = 0; j < 64; j++) {
            float2 v = wrow[j];
            Wreg[j] = pack2(v.x, v.y);
        }
    }

    const uint32_t hsm_u32 = smem_u32(hsm);

    unsigned target = 0;
    for (int s = 0; s < S_; s++) {
        const float* hsrc;
        size_t rstride;
        if (s == 0) { hsrc = h0 + (size_t)m0 * H_;                  rstride = H_; }
        else        { hsrc = hs + ((size_t)m0 * S_ + (s - 1)) * H_; rstride = (size_t)S_ * H_; }

        // stage h[16 batches][1024] into smem (4096 float4, 16 per thread)
#pragma unroll
        for (int i = 0; i < 16; i++) {
            int id = i * RTHR + t;     // 0..4095
            int r  = id >> 8;          // batch row 0..15
            int c  = id & 255;         // float4 col
            cp16(hsm_u32 + (uint32_t)(r * 1024 + c * 4) * 4,
                 hsrc + (size_t)r * rstride + c * 4);
        }
        CP_COMMIT();
        CP_WAIT(0);
        __syncthreads();

        // per-batch dot products: h broadcast from smem, W from registers
        for (int b = 0; b < 16; b++) {
            const ull* hrow = (const ull*)(hsm + b * 1024 + k0);
            ull a0 = 0, a1 = 0, a2 = 0, a3 = 0;
#pragma unroll
            for (int j = 0; j < 64; j += 4) {
                a0 = fma2(hrow[j + 0], Wreg[j + 0], a0);
                a1 = fma2(hrow[j + 1], Wreg[j + 1], a1);
                a2 = fma2(hrow[j + 2], Wreg[j + 2], a2);
                a3 = fma2(hrow[j + 3], Wreg[j + 3], a3);
            }
            float x0, x1;
            unpack2(add2(add2(a0, a1), add2(a2, a3)), x0, x1);
            part[(w * 16 + b) * PARTP + l] = x0 + x1;
        }
        __syncthreads();

        // reduce 8 k-partials, add xp, tanh, store. thread t -> (b, colpair)
        {
            const int b  = t >> 4;            // 0..15
            const int c0 = (t & 15) * 2;      // even col
            float s0 = 0.f, s1 = 0.f;
#pragma unroll
            for (int w8 = 0; w8 < 8; w8++) {
                s0 += part[(w8 * 16 + b) * PARTP + c0];
                s1 += part[(w8 * 16 + b) * PARTP + c0 + 1];
            }
            size_t orow = ((size_t)(m0 + b) * S_ + s) * H_ + n0 + c0;
            float2 xv = *(const float2*)(xp + orow);
            float2 hv;
            hv.x = tanh_acc(s0 + xv.x);
            hv.y = tanh_acc(s1 + xv.y);
            *(float2*)(hs + orow) = hv;
        }

        // grid barrier (monotonic counter; all RBLK blocks co-resident)
        target += RBLK;
        __syncthreads();
        if (t == 0) {
            __threadfence();
            atomicAdd(&g_bar, 1u);
            while (*(volatile unsigned*)&g_bar < target) { }
        }
        __syncthreads();
        __threadfence();
    }
}

// last_hidden[b][k] = hs[b][S-1][k]
__global__ void copy_last(const float* __restrict__ hs, float* __restrict__ out)
{
    int i = blockIdx.x * 256 + threadIdx.x;
    int b = i >> 10, k = i & (H_ - 1);
    out[i] = hs[((size_t)b * S_ + (S_ - 1)) * H_ + k];
}

// ---------------- launch ----------------
extern "C" void kernel_launch(void* const* d_in, const int* in_sizes, int n_in,
                              void* d_out, int out_size)
{
    const float* inputs = (const float*)d_in[0];
    const float* h0     = (const float*)d_in[1];
    const float* W_ih   = (const float*)d_in[2];
    const float* b_ih   = (const float*)d_in[3];
    const float* W_hh   = (const float*)d_in[4];
    const float* b_hh   = (const float*)d_in[5];
    const float* W_ho   = (const float*)d_in[6];
    const float* b_ho   = (const float*)d_in[7];
    float* out = (float*)d_out;

    float *xp, *hs;
    cudaGetSymbolAddress((void**)&xp, g_xp);
    cudaGetSymbolAddress((void**)&hs, g_hs);

    cudaFuncSetAttribute(rnn_recurrence,
                         cudaFuncAttributeMaxDynamicSharedMemorySize, REC_SMEM);

    zero_bar<<<1, 1>>>();

    // xp = inputs @ W_ih^T + b_ih + b_hh   (M=B*S, N=H, K=I)
    dim3 g1(H_ / 128, (B_ * S_) / 128);
    gemm_nt_bias<<<g1, 256>>>(inputs, W_ih, b_ih, b_hh, xp, B_ * S_, H_, I_);

    // sequential scan, persistent kernel
    rnn_recurrence<<<RBLK, RTHR, REC_SMEM>>>(xp, W_hh, h0, hs);

    // outputs = hs @ W_ho^T + b_ho         (M=B*S, N=O, K=H)
    dim3 g2(O_ / 128, (B_ * S_) / 128);
    gemm_nt_bias<<<g2, 256>>>(hs, W_ho, b_ho, nullptr, out, B_ * S_, O_, H_);

    // last_hidden appended after outputs
    copy_last<<<(B_ * H_) / 256, 256>>>(hs, out + (size_t)B_ * S_ * O_);
}

// round 6
// speedup vs baseline: 1.8536x; 1.1084x over previous
#include <cuda_runtime.h>
#include <cstdint>
#include <cstddef>

// Problem dims (fixed by the dataset)
#define B_ 64
#define S_ 1024
#define I_ 512
#define H_ 1024
#define O_ 512

typedef unsigned long long ull;

// ---------------- scratch (no cudaMalloc allowed) ----------------
__device__ float g_xp[(size_t)B_ * S_ * H_];  // x-projection (B*S, H)
__device__ float g_hs[(size_t)B_ * S_ * H_];  // hidden states [b][s][H]
__device__ unsigned g_bar4[4 * 32];           // 4 padded barrier counters

// ---------------- helpers ----------------
__device__ __forceinline__ ull fma2(ull a, ull b, ull c) {
    ull d;
    asm("fma.rn.f32x2 %0, %1, %2, %3;" : "=l"(d) : "l"(a), "l"(b), "l"(c));
    return d;
}
__device__ __forceinline__ ull add2(ull a, ull b) {
    ull d;
    asm("add.rn.f32x2 %0, %1, %2;" : "=l"(d) : "l"(a), "l"(b));
    return d;
}
__device__ __forceinline__ ull pack2(float x, float y) {
    ull d; asm("mov.b64 %0, {%1, %2};" : "=l"(d) : "f"(x), "f"(y)); return d;
}
__device__ __forceinline__ void unpack2(ull v, float& lo, float& hi) {
    asm("mov.b64 {%0, %1}, %2;" : "=f"(lo), "=f"(hi) : "l"(v));
}
__device__ __forceinline__ uint32_t smem_u32(const void* p) {
    uint32_t a;
    asm("{ .reg .u64 t; cvta.to.shared.u64 t, %1; cvt.u32.u64 %0, t; }"
        : "=r"(a) : "l"(p));
    return a;
}
__device__ __forceinline__ void cp16(uint32_t saddr, const void* g) {
    asm volatile("cp.async.cg.shared.global [%0], [%1], 16;" :: "r"(saddr), "l"(g));
}
#define CP_COMMIT() asm volatile("cp.async.commit_group;" ::: "memory")
#define CP_WAIT(n)  asm volatile("cp.async.wait_group %0;" :: "n"(n) : "memory")

// Accurate tanh, robust under --use_fast_math.
__device__ __forceinline__ float tanh_acc(float x) {
    float ax = fabsf(x);
    float e  = __expf(-2.0f * ax);
    float r  = (1.0f - e) / (1.0f + e);
    return copysignf(r, x);
}

__global__ void zero_bar() {
    if (threadIdx.x < 4 * 32) g_bar4[threadIdx.x] = 0u;
}

// ---------------- NT GEMM with f32x2 FMA ----------------
__global__ void __launch_bounds__(256)
gemm_nt_bias(const float* __restrict__ A, const float* __restrict__ Bm,
             const float* __restrict__ bias0, const float* __restrict__ bias1,
             float* __restrict__ C, int M, int N, int K)
{
    const int BK = 16;
    __shared__ float As[16][128 + 4];
    __shared__ float Bs[16][128 + 4];

    int t  = threadIdx.x;
    int tx = t & 15;
    int ty = t >> 4;
    int bm = blockIdx.y * 128;
    int bn = blockIdx.x * 128;

    ull acc2[8][4];
#pragma unroll
    for (int i = 0; i < 8; i++)
#pragma unroll
        for (int j = 0; j < 4; j++) acc2[i][j] = 0ull;

    for (int kc = 0; kc < K; kc += BK) {
#pragma unroll
        for (int i = 0; i < 2; i++) {
            int id = t + i * 256;
            int r  = id >> 2;
            int c4 = id & 3;
            float4 va = *(const float4*)(A  + (size_t)(bm + r) * K + kc + c4 * 4);
            As[c4 * 4 + 0][r] = va.x; As[c4 * 4 + 1][r] = va.y;
            As[c4 * 4 + 2][r] = va.z; As[c4 * 4 + 3][r] = va.w;
            float4 vb = *(const float4*)(Bm + (size_t)(bn + r) * K + kc + c4 * 4);
            Bs[c4 * 4 + 0][r] = vb.x; Bs[c4 * 4 + 1][r] = vb.y;
            Bs[c4 * 4 + 2][r] = vb.z; Bs[c4 * 4 + 3][r] = vb.w;
        }
        __syncthreads();
#pragma unroll
        for (int k = 0; k < BK; k++) {
            float4 a0 = *(const float4*)&As[k][ty * 8];
            float4 a1 = *(const float4*)&As[k][ty * 8 + 4];
            ulonglong2 b0 = *(const ulonglong2*)&Bs[k][tx * 8];
            ulonglong2 b1 = *(const ulonglong2*)&Bs[k][tx * 8 + 4];
            ull bb[4] = { b0.x, b0.y, b1.x, b1.y };
            ull a2[8];
            a2[0] = pack2(a0.x, a0.x); a2[1] = pack2(a0.y, a0.y);
            a2[2] = pack2(a0.z, a0.z); a2[3] = pack2(a0.w, a0.w);
            a2[4] = pack2(a1.x, a1.x); a2[5] = pack2(a1.y, a1.y);
            a2[6] = pack2(a1.z, a1.z); a2[7] = pack2(a1.w, a1.w);
#pragma unroll
            for (int i = 0; i < 8; i++)
#pragma unroll
                for (int j = 0; j < 4; j++)
                    acc2[i][j] = fma2(a2[i], bb[j], acc2[i][j]);
        }
        __syncthreads();
    }

    float bs[8];
#pragma unroll
    for (int j = 0; j < 8; j++) {
        int n = bn + tx * 8 + j;
        bs[j] = bias0[n] + (bias1 ? bias1[n] : 0.0f);
    }
#pragma unroll
    for (int i = 0; i < 8; i++) {
        float acc[8];
#pragma unroll
        for (int j = 0; j < 4; j++)
            unpack2(acc2[i][j], acc[2 * j], acc[2 * j + 1]);
        size_t row = (size_t)(bm + ty * 8 + i) * N + bn + tx * 8;
        float4 v0 = make_float4(acc[0] + bs[0], acc[1] + bs[1],
                                acc[2] + bs[2], acc[3] + bs[3]);
        float4 v1 = make_float4(acc[4] + bs[4], acc[5] + bs[5],
                                acc[6] + bs[6], acc[7] + bs[7]);
        *(float4*)(C + row)     = v0;
        *(float4*)(C + row + 4) = v1;
    }
}

// ---------------- persistent recurrence, W_hh in registers ----------------
// 128 blocks x 256 threads (1/SM). Block bx: cols n0=(bx>>2)*32, batches
// m0=(bx&3)*16. Warp w owns k-chunk [128w,128w+128); lane l owns column
// n0+l (64 f32x2 W registers, persistent). Per step each WARP cp.asyncs its
// own 8KB h-slice (no block sync before compute), computes 16 dots, writes
// k-partials; one syncthreads; 256 threads reduce+tanh+store; then a 32-way
// batch-group barrier (release/acquire, no membar.gl).
#define RBLK 128
#define RTHR 256
#define PARTP 33
#define HSM_F (8 * 16 * 128)                      // 16384 floats = 64KB
#define REC_SMEM ((HSM_F + 8 * 16 * PARTP) * 4)

__global__ void __launch_bounds__(RTHR, 1)
rnn_recurrence(const float* __restrict__ xp, const float* __restrict__ Whh,
               const float* __restrict__ h0, float* __restrict__ hs)
{
    extern __shared__ float sm[];
    float* hsm  = sm;                 // [warp][batch][128]
    float* part = sm + HSM_F;         // [8][16][PARTP]

    const int t  = threadIdx.x;
    const int bx = blockIdx.x;
    const int n0 = (bx >> 2) * 32;    // first col of this block
    const int grp = bx & 3;           // batch group
    const int m0 = grp * 16;          // first batch
    const int w  = t >> 5;            // warp: k-chunk owner
    const int l  = t & 31;            // lane: column owner
    const int k0 = w * 128;

    // epilogue mapping for this thread
    const int eb  = t >> 4;           // batch 0..15
    const int ec0 = (t & 15) * 2;     // even col

    // Load this lane's W_hh column-slice into registers (once).
    ull Wreg[64];
    {
        const float2* wrow = (const float2*)(Whh + (size_t)(n0 + l) * H_ + k0);
#pragma unroll
        for (int j = 0; j < 64; j++) {
            float2 v = wrow[j];
            Wreg[j] = pack2(v.x, v.y);
        }
    }

    // warp-private staging base (bytes): hsm[w][r][l*4]
    const uint32_t hw_u32 = smem_u32(hsm) + (uint32_t)(w * 16 * 128) * 4;
    volatile unsigned* bar = (volatile unsigned*)&g_bar4[grp * 32];

    unsigned target = 0;
    for (int s = 0; s < S_; s++) {
        const float* hsrc;
        size_t rstride;
        if (s == 0) { hsrc = h0 + (size_t)m0 * H_;                  rstride = H_; }
        else        { hsrc = hs + ((size_t)m0 * S_ + (s - 1)) * H_; rstride = (size_t)S_ * H_; }

        // warp-local stage: 16 rows x 512B of this warp's k-chunk
        const float* src0 = hsrc + k0 + l * 4;
#pragma unroll
        for (int r = 0; r < 16; r++) {
            cp16(hw_u32 + (uint32_t)(r * 128 + l * 4) * 4,
                 src0 + (size_t)r * rstride);
        }
        CP_COMMIT();

        // prefetch xp for this step's epilogue (hidden under compute)
        size_t orow = ((size_t)(m0 + eb) * S_ + s) * H_ + n0 + ec0;
        float2 xv = *(const float2*)(xp + orow);

        CP_WAIT(0);
        __syncwarp();

        // 16 dot-chunks: h broadcast from smem, W from registers
#pragma unroll 2
        for (int b = 0; b < 16; b++) {
            const ulonglong2* hrow = (const ulonglong2*)(hsm + (w * 16 + b) * 128);
            ull a0 = 0, a1 = 0, a2 = 0, a3 = 0;
#pragma unroll
            for (int j = 0; j < 32; j += 2) {
                ulonglong2 h2a = hrow[j];
                ulonglong2 h2b = hrow[j + 1];
                a0 = fma2(h2a.x, Wreg[2 * j + 0], a0);
                a1 = fma2(h2a.y, Wreg[2 * j + 1], a1);
                a2 = fma2(h2b.x, Wreg[2 * j + 2], a2);
                a3 = fma2(h2b.y, Wreg[2 * j + 3], a3);
            }
            float x0, x1;
            unpack2(add2(add2(a0, a1), add2(a2, a3)), x0, x1);
            part[(w * 16 + b) * PARTP + l] = x0 + x1;
        }
        __syncthreads();

        // reduce 8 k-partials, add xp, tanh, store
        {
            float s0 = 0.f, s1 = 0.f;
#pragma unroll
            for (int w8 = 0; w8 < 8; w8++) {
                s0 += part[(w8 * 16 + eb) * PARTP + ec0];
                s1 += part[(w8 * 16 + eb) * PARTP + ec0 + 1];
            }
            float2 hv;
            hv.x = tanh_acc(s0 + xv.x);
            hv.y = tanh_acc(s1 + xv.y);
            *(float2*)(hs + orow) = hv;
        }

        // 32-way batch-group barrier (release add + acquire spin)
        target += 32;
        __syncthreads();
        if (t == 0) {
            asm volatile("red.release.gpu.global.add.u32 [%0], %1;"
                         :: "l"(bar), "r"(1u) : "memory");
            unsigned v;
            do {
                asm volatile("ld.acquire.gpu.global.u32 %0, [%1];"
                             : "=r"(v) : "l"(bar) : "memory");
            } while (v < target);
        }
        __syncthreads();
    }
}

// last_hidden[b][k] = hs[b][S-1][k]
__global__ void copy_last(const float* __restrict__ hs, float* __restrict__ out)
{
    int i = blockIdx.x * 256 + threadIdx.x;
    int b = i >> 10, k = i & (H_ - 1);
    out[i] = hs[((size_t)b * S_ + (S_ - 1)) * H_ + k];
}

// ---------------- launch ----------------
extern "C" void kernel_launch(void* const* d_in, const int* in_sizes, int n_in,
                              void* d_out, int out_size)
{
    const float* inputs = (const float*)d_in[0];
    const float* h0     = (const float*)d_in[1];
    const float* W_ih   = (const float*)d_in[2];
    const float* b_ih   = (const float*)d_in[3];
    const float* W_hh   = (const float*)d_in[4];
    const float* b_hh   = (const float*)d_in[5];
    const float* W_ho   = (const float*)d_in[6];
    const float* b_ho   = (const float*)d_in[7];
    float* out = (float*)d_out;

    float *xp, *hs;
    cudaGetSymbolAddress((void**)&xp, g_xp);
    cudaGetSymbolAddress((void**)&hs, g_hs);

    cudaFuncSetAttribute(rnn_recurrence,
                         cudaFuncAttributeMaxDynamicSharedMemorySize, REC_SMEM);

    zero_bar<<<1, 128>>>();

    // xp = inputs @ W_ih^T + b_ih + b_hh   (M=B*S, N=H, K=I)
    dim3 g1(H_ / 128, (B_ * S_) / 128);
    gemm_nt_bias<<<g1, 256>>>(inputs, W_ih, b_ih, b_hh, xp, B_ * S_, H_, I_);

    // sequential scan, persistent kernel
    rnn_recurrence<<<RBLK, RTHR, REC_SMEM>>>(xp, W_hh, h0, hs);

    // outputs = hs @ W_ho^T + b_ho         (M=B*S, N=O, K=H)
    dim3 g2(O_ / 128, (B_ * S_) / 128);
    gemm_nt_bias<<<g2, 256>>>(hs, W_ho, b_ho, nullptr, out, B_ * S_, O_, H_);

    // last_hidden appended after outputs
    copy_last<<<(B_ * H_) / 256, 256>>>(hs, out + (size_t)B_ * S_ * O_);
}